// round 11
// baseline (speedup 1.0000x reference)
#include <cuda_runtime.h>
#include <math.h>
#include <stdint.h>

#define R 32
#define V 50257
#define VR (V * R)              // floats per i-slab (contiguous)
#define L4 (VR / 4)             // 402,056 float4 per slab
#define BATCH 1024
#define NSTEP 8
#define EPS 1e-10f

#define THREADS 256
#define PER_SLAB 20             // blocks per slab
#define NBLOCKS (PER_SLAB * R)  // 640 total; every block streams
#define GPB 4                   // of which 4 per slab also gather
#define W_G 18834               // chunk f4 for gather-duty blocks
#define W_S 20420               // chunk f4 for stream-only blocks
// 4*W_G + 16*W_S = 402,056 = L4  (exact)

#define DEPTH 5                 // bulk-copy ring stages (best-measured config)
#define STAGE_F4 512            // 8 KB per stage, 2 float4 per thread
#define STAGE_BYTES (STAGE_F4 * 16)

// Scratch (no allocation anywhere)
__device__ float g_M[R * R];    // zeroed by memset node each replay
__device__ float g_pt[BATCH];
__device__ unsigned int g_count = 0;   // reset by finalize each replay

// ---- PTX helpers -----------------------------------------------------------
__device__ __forceinline__ void mbar_init(uint32_t a, uint32_t cnt) {
    asm volatile("mbarrier.init.shared.b64 [%0], %1;" :: "r"(a), "r"(cnt) : "memory");
}
__device__ __forceinline__ void mbar_expect_tx(uint32_t a, uint32_t bytes) {
    asm volatile("mbarrier.arrive.expect_tx.shared.b64 _, [%0], %1;"
                 :: "r"(a), "r"(bytes) : "memory");
}
__device__ __forceinline__ void mbar_wait(uint32_t a, uint32_t parity) {
    uint32_t done;
    asm volatile("{\n\t.reg .pred p;\n\t"
                 "mbarrier.try_wait.parity.acquire.cta.shared::cta.b64 p, [%1], %2;\n\t"
                 "selp.b32 %0, 1, 0, p;\n\t}"
                 : "=r"(done) : "r"(a), "r"(parity) : "memory");
    if (!done) {
        asm volatile("{\n\t.reg .pred P1;\n\t"
                     "W_%=:\n\t"
                     "mbarrier.try_wait.parity.acquire.cta.shared::cta.b64 P1, [%0], %1, 0x989680;\n\t"
                     "@P1 bra.uni D_%=;\n\t"
                     "bra.uni W_%=;\n\t"
                     "D_%=:\n\t}" :: "r"(a), "r"(parity) : "memory");
    }
}
__device__ __forceinline__ void bulk_g2s(uint32_t smem_dst, const void* gsrc,
                                         uint32_t bytes, uint32_t mbar) {
    asm volatile("cp.async.bulk.shared::cluster.global.mbarrier::complete_tx::bytes "
                 "[%0], [%1], %2, [%3];"
                 :: "r"(smem_dst), "l"(gsrc), "r"(bytes), "r"(mbar) : "memory");
}

__global__ __launch_bounds__(THREADS)
void tjd_fused_kernel(const float* __restrict__ alpha,
                      const float* __restrict__ beta,
                      const float* __restrict__ core,
                      const int*   __restrict__ ids,
                      float* __restrict__ out, int out_size)
{
    const int bid = blockIdx.x;
    const int tid = threadIdx.x;

    __shared__ __align__(16) union SmemU {
        float4 buf[DEPTH][STAGE_F4];                      // 40 KB ring
        struct { float sM[R * R]; float sloss[THREADS]; } fin;
    } u;
    __shared__ __align__(8) unsigned long long mbar[DEPTH];
    __shared__ float sred[R];
    __shared__ float s_z;
    __shared__ int   s_last;

    // -------- region for this block --------
    const int slab = bid / PER_SLAB;
    const int k    = bid % PER_SLAB;
    const bool do_gather = (k < GPB);
    const int start = do_gather ? k * W_G
                                : GPB * W_G + (k - GPB) * W_S;
    const int W     = do_gather ? W_G : W_S;
    const int end   = start + W;
    const int nfull = W / STAGE_F4;

    const float4* slabp = (const float4*)(core + (size_t)slab * VR);
    const float4* reg0  = slabp + start;
    const uint32_t buf0  = (uint32_t)__cvta_generic_to_shared(&u.buf[0][0]);
    const uint32_t mbar0 = (uint32_t)__cvta_generic_to_shared(&mbar[0]);

    if (tid == 0) {
        #pragma unroll
        for (int s = 0; s < DEPTH; s++) mbar_init(mbar0 + 8u * s, 1u);
    }
    __syncthreads();

    // prologue copies FIRST: ring fills (via TMA) while the gather runs
    if (tid == 0) {
        #pragma unroll
        for (int s = 0; s < DEPTH; s++) {
            mbar_expect_tx(mbar0 + 8u * s, STAGE_BYTES);
            bulk_g2s(buf0 + (uint32_t)s * STAGE_BYTES,
                     reg0 + (size_t)s * STAGE_F4, STAGE_BYTES, mbar0 + 8u * s);
        }
    }

    // -------- gather prologue (4 blocks per slab): one warp per batch row ----
    if (do_gather) {
        const int row  = (slab * GPB + k) * (THREADS / 32) + (tid >> 5);
        const int lane = tid & 31;
        const int* myids = ids + row * NSTEP;

        float v = fmaxf(alpha[lane], 0.0f) + EPS;

        #pragma unroll 1
        for (int t = 0; t < NSTEP; t++) {
            const float* base = core + (size_t)myids[t] * R + lane;
            float g[R];
            #pragma unroll
            for (int q = 0; q < R; q++)
                g[q] = __ldg(base + (size_t)q * VR);
            float nv = 0.0f;
            #pragma unroll
            for (int q = 0; q < R; q++)
                nv = fmaf(__shfl_sync(0xffffffffu, v, q),
                          fmaxf(g[q], 0.0f) + EPS, nv);
            v = nv;
        }

        float pt = v * (fmaxf(beta[lane], 0.0f) + EPS);
        #pragma unroll
        for (int o = 16; o; o >>= 1)
            pt += __shfl_xor_sync(0xffffffffu, pt, o);
        if (lane == 0) g_pt[row] = pt;
    }

    // -------- streaming reduction over [start, end) --------
    float x0=0.f, y0=0.f, z0=0.f, w0=0.f;
    float x1=0.f, y1=0.f, z1=0.f, w1=0.f;

    #pragma unroll 1
    for (int st = 0; st < nfull; st++) {
        const int slot = st % DEPTH;
        mbar_wait(mbar0 + 8u * slot, (uint32_t)((st / DEPTH) & 1));

        // 2 float4 per thread, stride 256 (mod 8 == 0 -> fixed j-lanes)
        float4 g0 = u.buf[slot][tid];
        float4 g1 = u.buf[slot][tid + 256];
        x0 += fmaxf(g0.x,0.f); y0 += fmaxf(g0.y,0.f);
        z0 += fmaxf(g0.z,0.f); w0 += fmaxf(g0.w,0.f);
        x1 += fmaxf(g1.x,0.f); y1 += fmaxf(g1.y,0.f);
        z1 += fmaxf(g1.z,0.f); w1 += fmaxf(g1.w,0.f);

        __syncthreads();                      // slot fully consumed
        if (tid == 0 && st + DEPTH < nfull) {
            mbar_expect_tx(mbar0 + 8u * slot, STAGE_BYTES);
            bulk_g2s(buf0 + (uint32_t)slot * STAGE_BYTES,
                     reg0 + (size_t)(st + DEPTH) * STAGE_F4, STAGE_BYTES,
                     mbar0 + 8u * slot);
        }
    }
    // ragged tail via direct loads (offsets mult of 8 -> same j-phase)
    for (int idx = start + nfull * STAGE_F4 + tid; idx < end; idx += 256) {
        float4 g = __ldg(slabp + idx);
        x1 += fmaxf(g.x,0.f); y1 += fmaxf(g.y,0.f);
        z1 += fmaxf(g.z,0.f); w1 += fmaxf(g.w,0.f);
    }
    const float ax = x0 + x1, ay = y0 + y1, az = z0 + z1, aw = w0 + w1;

    // thread's j nibble depends on chunk start phase
    const int jb = ((start + tid) & 7) * 4;
    if (tid < R) sred[tid] = 0.0f;
    __syncthreads();
    atomicAdd(&sred[jb + 0], ax);
    atomicAdd(&sred[jb + 1], ay);
    atomicAdd(&sred[jb + 2], az);
    atomicAdd(&sred[jb + 3], aw);
    __syncthreads();
    if (tid < R)
        atomicAdd(&g_M[slab * R + tid], sred[tid]);   // g_M pre-zeroed by memset node

    // ------------------- last-block-done finalize -------------------
    __syncthreads();
    if (tid == 0) {
        __threadfence();
        s_last = (atomicAdd(&g_count, 1u) == (unsigned)(NBLOCKS - 1));
    }
    __syncthreads();
    if (!s_last) return;

    for (int e = tid; e < R * R; e += THREADS)
        u.fin.sM[e] = g_M[e] + (float)V * EPS;
    __syncthreads();

    if (tid < R) {
        float uu = fmaxf(alpha[tid], 0.0f) + EPS;
        #pragma unroll 1
        for (int s = 0; s < NSTEP; s++) {
            float nu = 0.0f;
            #pragma unroll
            for (int q = 0; q < R; q++)
                nu = fmaf(__shfl_sync(0xffffffffu, uu, q),
                          u.fin.sM[q * R + tid], nu);
            uu = nu;                 // overflows to +inf like fp32 reference
        }
        float z = uu * (fmaxf(beta[tid], 0.0f) + EPS);
        #pragma unroll
        for (int o = 16; o; o >>= 1)
            z += __shfl_xor_sync(0xffffffffu, z, o);
        if (tid == 0) s_z = z;
    }
    __syncthreads();

    const float z = s_z;
    float lacc = 0.0f;
    for (int row = tid; row < BATCH; row += THREADS) {
        const float prob = g_pt[row] / z;
        if (out_size >= BATCH + 1)  out[1 + row] = prob;
        else if (out_size == BATCH) out[row]     = prob;
        lacc -= logf(prob + EPS);
    }
    u.fin.sloss[tid] = lacc;
    __syncthreads();
    #pragma unroll
    for (int s = THREADS / 2; s > 0; s >>= 1) {
        if (tid < s) u.fin.sloss[tid] += u.fin.sloss[tid + s];
        __syncthreads();
    }
    if (tid == 0) {
        if (out_size != BATCH) out[0] = u.fin.sloss[0] / (float)BATCH;
        g_count = 0;
    }
}

// ---------------------------------------------------------------------------
extern "C" void kernel_launch(void* const* d_in, const int* in_sizes, int n_in,
                              void* d_out, int out_size) {
    const float* alpha = (const float*)d_in[0];   // (32,)
    const float* beta  = (const float*)d_in[1];   // (32,)
    const float* core  = (const float*)d_in[2];   // (32, 50257, 32)
    const int*   ids   = (const int*)  d_in[3];   // (1024, 8)

    // zero the M accumulator via a graph-capturable memset node
    void* gM = nullptr;
    cudaGetSymbolAddress(&gM, g_M);
    cudaMemsetAsync(gM, 0, R * R * sizeof(float));

    tjd_fused_kernel<<<NBLOCKS, THREADS>>>(alpha, beta, core, ids,
                                           (float*)d_out, out_size);
}

// round 12
// speedup vs baseline: 1.0828x; 1.0828x over previous
#include <cuda_runtime.h>
#include <math.h>
#include <stdint.h>

#define R 32
#define V 50257
#define VR (V * R)              // floats per i-slab (contiguous)
#define L4 (VR / 4)             // 402,056 float4 per slab
#define BATCH 1024
#define NSTEP 8
#define EPS 1e-10f

#define THREADS 256
#define GATHER_BLOCKS 128       // 1024 warps = 1 / batch row
#define RED_BX 16               // reduction chunks per slab
#define RED_BLOCKS (RED_BX * R)               // 512
#define NBLOCKS (GATHER_BLOCKS + RED_BLOCKS)  // 640 (one wave)
#define CHUNK_F4 25136          // per-chunk float4 (mod 8 == 0), last clipped

#define DEPTH 5                 // bulk-copy ring stages (best-measured config)
#define STAGE_F4 512            // 8 KB per stage, 2 float4 per thread
#define STAGE_BYTES (STAGE_F4 * 16)

// Scratch (no allocation anywhere)
__device__ float g_M[R * R];    // zeroed by memset node each replay
__device__ float g_pt[BATCH];
__device__ unsigned int g_count = 0;   // reset by finalize each replay

// ---- PTX helpers -----------------------------------------------------------
__device__ __forceinline__ void mbar_init(uint32_t a, uint32_t cnt) {
    asm volatile("mbarrier.init.shared.b64 [%0], %1;" :: "r"(a), "r"(cnt) : "memory");
}
__device__ __forceinline__ void mbar_expect_tx(uint32_t a, uint32_t bytes) {
    asm volatile("mbarrier.arrive.expect_tx.shared.b64 _, [%0], %1;"
                 :: "r"(a), "r"(bytes) : "memory");
}
__device__ __forceinline__ void mbar_wait(uint32_t a, uint32_t parity) {
    uint32_t done;
    asm volatile("{\n\t.reg .pred p;\n\t"
                 "mbarrier.try_wait.parity.acquire.cta.shared::cta.b64 p, [%1], %2;\n\t"
                 "selp.b32 %0, 1, 0, p;\n\t}"
                 : "=r"(done) : "r"(a), "r"(parity) : "memory");
    if (!done) {
        asm volatile("{\n\t.reg .pred P1;\n\t"
                     "W_%=:\n\t"
                     "mbarrier.try_wait.parity.acquire.cta.shared::cta.b64 P1, [%0], %1, 0x989680;\n\t"
                     "@P1 bra.uni D_%=;\n\t"
                     "bra.uni W_%=;\n\t"
                     "D_%=:\n\t}" :: "r"(a), "r"(parity) : "memory");
    }
}
__device__ __forceinline__ void bulk_g2s(uint32_t smem_dst, const void* gsrc,
                                         uint32_t bytes, uint32_t mbar) {
    asm volatile("cp.async.bulk.shared::cluster.global.mbarrier::complete_tx::bytes "
                 "[%0], [%1], %2, [%3];"
                 :: "r"(smem_dst), "l"(gsrc), "r"(bytes), "r"(mbar) : "memory");
}

__global__ __launch_bounds__(THREADS)
void tjd_fused_kernel(const float* __restrict__ alpha,
                      const float* __restrict__ beta,
                      const float* __restrict__ core,
                      const int*   __restrict__ ids,
                      float* __restrict__ out, int out_size)
{
    const int bid = blockIdx.x;
    const int tid = threadIdx.x;

    // 40 KB bulk ring unioned with finalize scratch (used only after drain).
    __shared__ __align__(16) union SmemU {
        float4 buf[DEPTH][STAGE_F4];                      // 40 KB
        struct { float sM[R * R]; float sloss[THREADS]; } fin;
    } u;
    __shared__ __align__(8) unsigned long long mbar[DEPTH];
    __shared__ float sred[R];
    __shared__ float s_z;
    __shared__ int   s_last;

    if (bid < GATHER_BLOCKS) {
        // ---------------- gather/chain: one warp per batch row ----------------
        const int row  = bid * (THREADS / 32) + (tid >> 5);
        const int lane = tid & 31;
        const int* myids = ids + row * NSTEP;

        float v = fmaxf(alpha[lane], 0.0f) + EPS;

        #pragma unroll 1
        for (int t = 0; t < NSTEP; t++) {
            const float* base = core + (size_t)myids[t] * R + lane;
            float g[R];
            #pragma unroll
            for (int k = 0; k < R; k++)
                g[k] = __ldg(base + (size_t)k * VR);
            float nv = 0.0f;
            #pragma unroll
            for (int k = 0; k < R; k++)
                nv = fmaf(__shfl_sync(0xffffffffu, v, k),
                          fmaxf(g[k], 0.0f) + EPS, nv);
            v = nv;
        }

        float pt = v * (fmaxf(beta[lane], 0.0f) + EPS);
        #pragma unroll
        for (int o = 16; o; o >>= 1)
            pt += __shfl_xor_sync(0xffffffffu, pt, o);
        if (lane == 0) g_pt[row] = pt;
    } else {
        // ------ reduction via TMA-path bulk copies: M[i][j] = sum_v relu ------
        const int rb = bid - GATHER_BLOCKS;
        const int i  = rb / RED_BX;
        const int bx = rb % RED_BX;

        const float4* slab = (const float4*)(core + (size_t)i * VR);
        const int start = bx * CHUNK_F4;
        const int end   = (start + CHUNK_F4 < L4) ? start + CHUNK_F4 : L4;
        const int nfull = (end - start) / STAGE_F4;
        const float4* reg0 = slab + start;

        const uint32_t buf0  = (uint32_t)__cvta_generic_to_shared(&u.buf[0][0]);
        const uint32_t mbar0 = (uint32_t)__cvta_generic_to_shared(&mbar[0]);

        if (tid == 0) {
            #pragma unroll
            for (int s = 0; s < DEPTH; s++) mbar_init(mbar0 + 8u * s, 1u);
        }
        __syncthreads();

        if (tid == 0) {
            const int pre = (nfull < DEPTH) ? nfull : DEPTH;
            for (int s = 0; s < pre; s++) {
                mbar_expect_tx(mbar0 + 8u * s, STAGE_BYTES);
                bulk_g2s(buf0 + (uint32_t)s * STAGE_BYTES,
                         reg0 + (size_t)s * STAGE_F4, STAGE_BYTES,
                         mbar0 + 8u * s);
            }
        }

        float x0=0.f, y0=0.f, z0=0.f, w0=0.f;
        float x1=0.f, y1=0.f, z1=0.f, w1=0.f;

        #pragma unroll 1
        for (int st = 0; st < nfull; st++) {
            const int slot = st % DEPTH;
            mbar_wait(mbar0 + 8u * slot, (uint32_t)((st / DEPTH) & 1));

            // 2 float4 per thread, stride 256 (mod 8 == 0 -> fixed j-lanes)
            float4 g0 = u.buf[slot][tid];
            float4 g1 = u.buf[slot][tid + 256];
            x0 += fmaxf(g0.x,0.f); y0 += fmaxf(g0.y,0.f);
            z0 += fmaxf(g0.z,0.f); w0 += fmaxf(g0.w,0.f);
            x1 += fmaxf(g1.x,0.f); y1 += fmaxf(g1.y,0.f);
            z1 += fmaxf(g1.z,0.f); w1 += fmaxf(g1.w,0.f);

            __syncthreads();                      // slot fully consumed
            if (tid == 0 && st + DEPTH < nfull) {
                mbar_expect_tx(mbar0 + 8u * slot, STAGE_BYTES);
                bulk_g2s(buf0 + (uint32_t)slot * STAGE_BYTES,
                         reg0 + (size_t)(st + DEPTH) * STAGE_F4, STAGE_BYTES,
                         mbar0 + 8u * slot);
            }
        }
        // ragged tail via direct loads (offsets stay mod 8 -> same j mapping)
        for (int idx = start + nfull * STAGE_F4 + tid; idx < end; idx += 256) {
            float4 g = __ldg(slab + idx);
            x1 += fmaxf(g.x,0.f); y1 += fmaxf(g.y,0.f);
            z1 += fmaxf(g.z,0.f); w1 += fmaxf(g.w,0.f);
        }
        const float ax = x0 + x1, ay = y0 + y1, az = z0 + z1, aw = w0 + w1;

        // start % 8 == 0 -> thread's j nibble is (tid & 7) * 4
        const int jb = (tid & 7) * 4;
        if (tid < R) sred[tid] = 0.0f;
        __syncthreads();
        atomicAdd(&sred[jb + 0], ax);
        atomicAdd(&sred[jb + 1], ay);
        atomicAdd(&sred[jb + 2], az);
        atomicAdd(&sred[jb + 3], aw);
        __syncthreads();
        if (tid < R)
            atomicAdd(&g_M[i * R + tid], sred[tid]);  // g_M zeroed by memset node
    }

    // ------------------- last-block-done finalize -------------------
    __syncthreads();
    if (tid == 0) {
        __threadfence();
        s_last = (atomicAdd(&g_count, 1u) == (unsigned)(NBLOCKS - 1));
    }
    __syncthreads();
    if (!s_last) return;

    for (int e = tid; e < R * R; e += THREADS)
        u.fin.sM[e] = g_M[e] + (float)V * EPS;
    __syncthreads();

    if (tid < R) {
        float uu = fmaxf(alpha[tid], 0.0f) + EPS;
        #pragma unroll 1
        for (int s = 0; s < NSTEP; s++) {
            float nu = 0.0f;
            #pragma unroll
            for (int k = 0; k < R; k++)
                nu = fmaf(__shfl_sync(0xffffffffu, uu, k),
                          u.fin.sM[k * R + tid], nu);
            uu = nu;                 // overflows to +inf like fp32 reference
        }
        float z = uu * (fmaxf(beta[tid], 0.0f) + EPS);
        #pragma unroll
        for (int o = 16; o; o >>= 1)
            z += __shfl_xor_sync(0xffffffffu, z, o);
        if (tid == 0) s_z = z;
    }
    __syncthreads();

    const float z = s_z;
    float lacc = 0.0f;
    for (int row = tid; row < BATCH; row += THREADS) {
        const float prob = g_pt[row] / z;
        if (out_size >= BATCH + 1)  out[1 + row] = prob;
        else if (out_size == BATCH) out[row]     = prob;
        lacc -= logf(prob + EPS);
    }
    u.fin.sloss[tid] = lacc;
    __syncthreads();
    #pragma unroll
    for (int s = THREADS / 2; s > 0; s >>= 1) {
        if (tid < s) u.fin.sloss[tid] += u.fin.sloss[tid + s];
        __syncthreads();
    }
    if (tid == 0) {
        if (out_size != BATCH) out[0] = u.fin.sloss[0] / (float)BATCH;
        g_count = 0;
    }
}

// ---------------------------------------------------------------------------
extern "C" void kernel_launch(void* const* d_in, const int* in_sizes, int n_in,
                              void* d_out, int out_size) {
    const float* alpha = (const float*)d_in[0];   // (32,)
    const float* beta  = (const float*)d_in[1];   // (32,)
    const float* core  = (const float*)d_in[2];   // (32, 50257, 32)
    const int*   ids   = (const int*)  d_in[3];   // (1024, 8)

    // zero the M accumulator via a graph-capturable memset node
    void* gM = nullptr;
    cudaGetSymbolAddress(&gM, g_M);
    cudaMemsetAsync(gM, 0, R * R * sizeof(float));

    tjd_fused_kernel<<<NBLOCKS, THREADS>>>(alpha, beta, core, ids,
                                           (float*)d_out, out_size);
}

// round 13
// speedup vs baseline: 1.1051x; 1.0206x over previous
#include <cuda_runtime.h>
#include <math.h>
#include <stdint.h>

#define R 32
#define V 50257
#define VR (V * R)              // floats per i-slab (contiguous)
#define L4 (VR / 4)             // 402,056 float4 per slab
#define BATCH 1024
#define NSTEP 8
#define EPS 1e-10f

#define THREADS 256
#define GATHER_BLOCKS 128       // 1024 warps = 1 / batch row
#define RED_BX 16               // reduction chunks per slab
#define RED_BLOCKS (RED_BX * R)               // 512
#define NBLOCKS (GATHER_BLOCKS + RED_BLOCKS)  // 640 (one wave)
#define CHUNK_F4 25136          // per-chunk float4 (mod 8 == 0), last clipped

#define DEPTH 5                 // bulk-copy ring stages (best-measured config)
#define STAGE_F4 512            // 8 KB per stage, 2 float4 per thread
#define STAGE_BYTES (STAGE_F4 * 16)

// Scratch (no allocation anywhere). g_M/g_count start zero (module load) and
// are reset to zero by the finalize path each call -> graph-replay safe with
// no memset node.
__device__ float g_M[R * R];
__device__ float g_pt[BATCH];
__device__ unsigned int g_count = 0;

// ---- PTX helpers -----------------------------------------------------------
__device__ __forceinline__ void mbar_init(uint32_t a, uint32_t cnt) {
    asm volatile("mbarrier.init.shared.b64 [%0], %1;" :: "r"(a), "r"(cnt) : "memory");
}
__device__ __forceinline__ void mbar_expect_tx(uint32_t a, uint32_t bytes) {
    asm volatile("mbarrier.arrive.expect_tx.shared.b64 _, [%0], %1;"
                 :: "r"(a), "r"(bytes) : "memory");
}
__device__ __forceinline__ void mbar_wait(uint32_t a, uint32_t parity) {
    uint32_t done;
    asm volatile("{\n\t.reg .pred p;\n\t"
                 "mbarrier.try_wait.parity.acquire.cta.shared::cta.b64 p, [%1], %2;\n\t"
                 "selp.b32 %0, 1, 0, p;\n\t}"
                 : "=r"(done) : "r"(a), "r"(parity) : "memory");
    if (!done) {
        asm volatile("{\n\t.reg .pred P1;\n\t"
                     "W_%=:\n\t"
                     "mbarrier.try_wait.parity.acquire.cta.shared::cta.b64 P1, [%0], %1, 0x989680;\n\t"
                     "@P1 bra.uni D_%=;\n\t"
                     "bra.uni W_%=;\n\t"
                     "D_%=:\n\t}" :: "r"(a), "r"(parity) : "memory");
    }
}
__device__ __forceinline__ void bulk_g2s(uint32_t smem_dst, const void* gsrc,
                                         uint32_t bytes, uint32_t mbar) {
    asm volatile("cp.async.bulk.shared::cluster.global.mbarrier::complete_tx::bytes "
                 "[%0], [%1], %2, [%3];"
                 :: "r"(smem_dst), "l"(gsrc), "r"(bytes), "r"(mbar) : "memory");
}

__global__ __launch_bounds__(THREADS)
void tjd_fused_kernel(const float* __restrict__ alpha,
                      const float* __restrict__ beta,
                      const float* __restrict__ core,
                      const int*   __restrict__ ids,
                      float* __restrict__ out, int out_size)
{
    const int bid = blockIdx.x;
    const int tid = threadIdx.x;

    // 40 KB bulk ring unioned with finalize scratch (used only after drain).
    __shared__ __align__(16) union SmemU {
        float4 buf[DEPTH][STAGE_F4];                      // 40 KB
        struct { float sM[R * R]; float sloss[THREADS]; } fin;
    } u;
    __shared__ __align__(8) unsigned long long mbar[DEPTH];
    __shared__ float sred[R];
    __shared__ float s_z;
    __shared__ int   s_last;

    if (bid < GATHER_BLOCKS) {
        // ---------------- gather/chain: one warp per batch row ----------------
        const int row  = bid * (THREADS / 32) + (tid >> 5);
        const int lane = tid & 31;
        const int* myids = ids + row * NSTEP;

        float v = fmaxf(alpha[lane], 0.0f) + EPS;

        #pragma unroll 1
        for (int t = 0; t < NSTEP; t++) {
            const float* base = core + (size_t)myids[t] * R + lane;
            float g[R];
            #pragma unroll
            for (int k = 0; k < R; k++)
                g[k] = __ldg(base + (size_t)k * VR);
            float nv = 0.0f;
            #pragma unroll
            for (int k = 0; k < R; k++)
                nv = fmaf(__shfl_sync(0xffffffffu, v, k),
                          fmaxf(g[k], 0.0f) + EPS, nv);
            v = nv;
        }

        float pt = v * (fmaxf(beta[lane], 0.0f) + EPS);
        #pragma unroll
        for (int o = 16; o; o >>= 1)
            pt += __shfl_xor_sync(0xffffffffu, pt, o);
        if (lane == 0) g_pt[row] = pt;
    } else {
        // ------ reduction via TMA-path bulk copies: M[i][j] = sum_v relu ------
        const int rb = bid - GATHER_BLOCKS;
        const int i  = rb / RED_BX;
        const int bx = rb % RED_BX;

        const float4* slab = (const float4*)(core + (size_t)i * VR);
        const int start = bx * CHUNK_F4;
        const int end   = (start + CHUNK_F4 < L4) ? start + CHUNK_F4 : L4;
        const int nfull = (end - start) / STAGE_F4;
        const float4* reg0 = slab + start;

        const uint32_t buf0  = (uint32_t)__cvta_generic_to_shared(&u.buf[0][0]);
        const uint32_t mbar0 = (uint32_t)__cvta_generic_to_shared(&mbar[0]);

        if (tid == 0) {
            #pragma unroll
            for (int s = 0; s < DEPTH; s++) mbar_init(mbar0 + 8u * s, 1u);
        }
        __syncthreads();

        if (tid == 0) {
            const int pre = (nfull < DEPTH) ? nfull : DEPTH;
            for (int s = 0; s < pre; s++) {
                mbar_expect_tx(mbar0 + 8u * s, STAGE_BYTES);
                bulk_g2s(buf0 + (uint32_t)s * STAGE_BYTES,
                         reg0 + (size_t)s * STAGE_F4, STAGE_BYTES,
                         mbar0 + 8u * s);
            }
        }

        float x0=0.f, y0=0.f, z0=0.f, w0=0.f;
        float x1=0.f, y1=0.f, z1=0.f, w1=0.f;

        #pragma unroll 1
        for (int st = 0; st < nfull; st++) {
            const int slot = st % DEPTH;
            mbar_wait(mbar0 + 8u * slot, (uint32_t)((st / DEPTH) & 1));

            // 2 float4 per thread, stride 256 (mod 8 == 0 -> fixed j-lanes)
            float4 g0 = u.buf[slot][tid];
            float4 g1 = u.buf[slot][tid + 256];
            x0 += fmaxf(g0.x,0.f); y0 += fmaxf(g0.y,0.f);
            z0 += fmaxf(g0.z,0.f); w0 += fmaxf(g0.w,0.f);
            x1 += fmaxf(g1.x,0.f); y1 += fmaxf(g1.y,0.f);
            z1 += fmaxf(g1.z,0.f); w1 += fmaxf(g1.w,0.f);

            __syncthreads();                      // slot fully consumed
            if (tid == 0 && st + DEPTH < nfull) {
                mbar_expect_tx(mbar0 + 8u * slot, STAGE_BYTES);
                bulk_g2s(buf0 + (uint32_t)slot * STAGE_BYTES,
                         reg0 + (size_t)(st + DEPTH) * STAGE_F4, STAGE_BYTES,
                         mbar0 + 8u * slot);
            }
        }
        // ragged tail via direct loads (offsets stay mod 8 -> same j mapping)
        for (int idx = start + nfull * STAGE_F4 + tid; idx < end; idx += 256) {
            float4 g = __ldg(slab + idx);
            x1 += fmaxf(g.x,0.f); y1 += fmaxf(g.y,0.f);
            z1 += fmaxf(g.z,0.f); w1 += fmaxf(g.w,0.f);
        }
        const float ax = x0 + x1, ay = y0 + y1, az = z0 + z1, aw = w0 + w1;

        // start % 8 == 0 -> thread's j nibble is (tid & 7) * 4
        const int jb = (tid & 7) * 4;
        if (tid < R) sred[tid] = 0.0f;
        __syncthreads();
        atomicAdd(&sred[jb + 0], ax);
        atomicAdd(&sred[jb + 1], ay);
        atomicAdd(&sred[jb + 2], az);
        atomicAdd(&sred[jb + 3], aw);
        __syncthreads();
        if (tid < R)
            atomicAdd(&g_M[i * R + tid], sred[tid]);  // g_M zero at call entry
    }

    // ------------------- last-block-done finalize -------------------
    __syncthreads();
    if (tid == 0) {
        __threadfence();
        s_last = (atomicAdd(&g_count, 1u) == (unsigned)(NBLOCKS - 1));
    }
    __syncthreads();
    if (!s_last) return;

    // consume g_M and reset it for the next graph replay (self-cleaning)
    for (int e = tid; e < R * R; e += THREADS) {
        u.fin.sM[e] = g_M[e] + (float)V * EPS;
        g_M[e] = 0.0f;
    }
    __syncthreads();

    if (tid < R) {
        float uu = fmaxf(alpha[tid], 0.0f) + EPS;
        #pragma unroll 1
        for (int s = 0; s < NSTEP; s++) {
            float nu = 0.0f;
            #pragma unroll
            for (int k = 0; k < R; k++)
                nu = fmaf(__shfl_sync(0xffffffffu, uu, k),
                          u.fin.sM[k * R + tid], nu);
            uu = nu;                 // overflows to +inf like fp32 reference
        }
        float z = uu * (fmaxf(beta[tid], 0.0f) + EPS);
        #pragma unroll
        for (int o = 16; o; o >>= 1)
            z += __shfl_xor_sync(0xffffffffu, z, o);
        if (tid == 0) s_z = z;
    }
    __syncthreads();

    const float z = s_z;
    float lacc = 0.0f;
    for (int row = tid; row < BATCH; row += THREADS) {
        const float prob = g_pt[row] / z;
        if (out_size >= BATCH + 1)  out[1 + row] = prob;
        else if (out_size == BATCH) out[row]     = prob;
        lacc -= logf(prob + EPS);
    }
    u.fin.sloss[tid] = lacc;
    __syncthreads();
    #pragma unroll
    for (int s = THREADS / 2; s > 0; s >>= 1) {
        if (tid < s) u.fin.sloss[tid] += u.fin.sloss[tid + s];
        __syncthreads();
    }
    if (tid == 0) {
        if (out_size != BATCH) out[0] = u.fin.sloss[0] / (float)BATCH;
        g_count = 0;
    }
}

// ---------------------------------------------------------------------------
extern "C" void kernel_launch(void* const* d_in, const int* in_sizes, int n_in,
                              void* d_out, int out_size) {
    const float* alpha = (const float*)d_in[0];   // (32,)
    const float* beta  = (const float*)d_in[1];   // (32,)
    const float* core  = (const float*)d_in[2];   // (32, 50257, 32)
    const int*   ids   = (const int*)  d_in[3];   // (1024, 8)

    tjd_fused_kernel<<<NBLOCKS, THREADS>>>(alpha, beta, core, ids,
                                           (float*)d_out, out_size);
}